// round 4
// baseline (speedup 1.0000x reference)
#include <cuda_runtime.h>

// ContourIntegrationLayer: depthwise 3x3 conv (center tap zeroed) + residual.
// x: [B=32, H=56, W=56, C=256] fp32 NHWC, kernel: [3,3,256] fp32.
// Residual folded by forcing the center weight to 1.0.
//
// Sync-free register-accumulator design with a 3-slot register ring.
// Round 4: 112-thread CTAs (W split in halves, 1-col halo), 5 CTAs/SM,
// 2048-block grid (2.77 waves), streaming stores.
// Block: (8 channel-float4, 14 w-pairs) = 112 threads.
// Grid:  (8 cblk * 2 whalf) x 4 hchunk x 32 batch = 2048 blocks.

#define B_  32
#define H_  56
#define W_  56
#define C_  256
#define CG  8
#define HC  14                   // output rows per block
#define WP  14                   // w-pairs per block (28 columns)
#define CQ  (C_ / 4)             // 64 float4 per pixel
#define ROWF4 (W_ * CQ)          // 3584 float4 per image row

__global__ __launch_bounds__(112, 5)
void contour_kernel(const float4* __restrict__ x,
                    const float*  __restrict__ krn,
                    float4*       __restrict__ out)
{
    const int tx  = threadIdx.x;             // 0..7  channel group
    const int ty  = threadIdx.y;             // 0..13 w-pair
    const int cb  = blockIdx.x & 7;          // channel block
    const int wh  = blockIdx.x >> 3;         // 0..1  w half
    const int hch = blockIdx.y;              // 0..3  H chunk
    const int b   = blockIdx.z;              // batch
    const int c   = cb * 32 + tx * 4;

    // 3x3 per-channel weights; center tap := 1.0 (residual fold)
    float4 Wt[3][3];
#pragma unroll
    for (int ky = 0; ky < 3; ky++)
#pragma unroll
        for (int kx = 0; kx < 3; kx++)
            Wt[ky][kx] = *reinterpret_cast<const float4*>(krn + (ky * 3 + kx) * C_ + c);
    Wt[1][1] = make_float4(1.f, 1.f, 1.f, 1.f);

    const int  w0  = wh * (2 * WP) + ty * 2;
    const bool wlo = (w0 > 0);               // col w0-1 exists
    const bool whi = (w0 + 2 < W_);          // col w1+1 exists
    const float4 z = make_float4(0.f, 0.f, 0.f, 0.f);

    const size_t base = (size_t)b * H_ * ROWF4 + (size_t)w0 * CQ + cb * CG + tx;
    const float4* xb = x   + base;
    float4*       ob = out + base;

    const int hs = hch * HC;

    // row loader: cols w0-1, w0, w0+1, w0+2 of input row r (zeros OOB)
    auto load = [&](int r, float4* v) {
        if ((unsigned)r < (unsigned)H_) {
            const float4* p = xb + (size_t)r * ROWF4;
            v[0] = wlo ? p[-CQ]    : z;
            v[1] = p[0];
            v[2] = p[CQ];
            v[3] = whi ? p[2 * CQ] : z;
        } else {
            v[0] = z; v[1] = z; v[2] = z; v[3] = z;
        }
    };

    // horizontal conv of v[0..3] with weight row k, accumulated into (o0,o1)
    auto hconv = [&](float4& o0, float4& o1, const float4 k0, const float4 k1,
                     const float4 k2, const float4* v) {
        o0.x = fmaf(k0.x, v[0].x, fmaf(k1.x, v[1].x, fmaf(k2.x, v[2].x, o0.x)));
        o0.y = fmaf(k0.y, v[0].y, fmaf(k1.y, v[1].y, fmaf(k2.y, v[2].y, o0.y)));
        o0.z = fmaf(k0.z, v[0].z, fmaf(k1.z, v[1].z, fmaf(k2.z, v[2].z, o0.z)));
        o0.w = fmaf(k0.w, v[0].w, fmaf(k1.w, v[1].w, fmaf(k2.w, v[2].w, o0.w)));
        o1.x = fmaf(k0.x, v[1].x, fmaf(k1.x, v[2].x, fmaf(k2.x, v[3].x, o1.x)));
        o1.y = fmaf(k0.y, v[1].y, fmaf(k1.y, v[2].y, fmaf(k2.y, v[3].y, o1.y)));
        o1.z = fmaf(k0.z, v[1].z, fmaf(k1.z, v[2].z, fmaf(k2.z, v[3].z, o1.z)));
        o1.w = fmaf(k0.w, v[1].w, fmaf(k1.w, v[2].w, fmaf(k2.w, v[3].w, o1.w)));
    };

    float4 buf[3][4];               // 3-slot register row ring
    float4 am0 = z, am1 = z;        // partial accum for output row r-1
    float4 ac0 = z, ac1 = z;        // partial accum for output row r

    // prolog: rows hs-1, hs, hs+1 into slots 0,1,2
    load(hs - 1, buf[0]);
    load(hs,     buf[1]);
    load(hs + 1, buf[2]);

    // iterations i = 0..HC+1 consume input rows hs-1 .. hs+HC
#pragma unroll
    for (int i = 0; i < HC + 2; i++) {
        const int r = hs - 1 + i;
        const float4* cur = buf[i % 3];

        // complete output row r-1 with this row's bottom-tap contribution
        float4 d0 = am0, d1 = am1;
        hconv(d0, d1, Wt[2][0], Wt[2][1], Wt[2][2], cur);
        if (i >= 2) {               // output rows hs .. hs+HC-1
            float4* po = ob + (size_t)(r - 1) * ROWF4;
            __stcs(po, d0);         // streaming store: written once, never read
            __stcs(po + CQ, d1);
        }

        // roll accumulators: am <- ac + middle-tap, ac <- top-tap (fresh)
        am0 = ac0; am1 = ac1;
        hconv(am0, am1, Wt[1][0], Wt[1][1], Wt[1][2], cur);
        ac0 = z; ac1 = z;
        hconv(ac0, ac1, Wt[0][0], Wt[0][1], Wt[0][2], cur);

        // refill the slot just consumed with row r+3 (consumed at i+3)
        if (i <= HC - 2)
            load(r + 3, buf[i % 3]);
    }
}

extern "C" void kernel_launch(void* const* d_in, const int* in_sizes, int n_in,
                              void* d_out, int out_size)
{
    const float4* x   = (const float4*)d_in[0];
    const float*  krn = (const float*)d_in[1];
    float4*       out = (float4*)d_out;

    dim3 block(CG, WP, 1);                       // 112 threads
    dim3 grid(16, H_ / HC, B_);                  // 16 x 4 x 32 = 2048 blocks
    contour_kernel<<<grid, block>>>(x, krn, out);
}

// round 5
// speedup vs baseline: 1.0968x; 1.0968x over previous
#include <cuda_runtime.h>

// ContourIntegrationLayer: depthwise 3x3 conv (center tap zeroed) + residual.
// x: [B=32, H=56, W=56, C=256] fp32 NHWC, kernel: [3,3,256] fp32.
// Residual folded by forcing the center weight to 1.0.
//
// Round 5: Round-3 shape (224 threads, occ 2) + 4-slot register row ring:
//   row r's 4x LDG.128 are issued at iteration i and consumed at i+4 -> three
//   full rows (12 LDG.128/thread) in flight. No SMEM, no __syncthreads.
// Block: (8 channel-float4, 28 w-pairs) = 224 threads.
// Grid:  8 channel-blocks x 4 H-chunks x 32 batches = 1024 blocks.

#define B_  32
#define H_  56
#define W_  56
#define C_  256
#define CG  8
#define HC  14                   // output rows per block
#define CQ  (C_ / 4)             // 64 float4 per pixel
#define ROWF4 (W_ * CQ)          // 3584 float4 per image row

__global__ __launch_bounds__(224, 2)
void contour_kernel(const float4* __restrict__ x,
                    const float*  __restrict__ krn,
                    float4*       __restrict__ out)
{
    const int tx  = threadIdx.x;     // 0..7  channel group
    const int ty  = threadIdx.y;     // 0..27 w-pair
    const int cb  = blockIdx.x;      // 0..7  channel block
    const int hch = blockIdx.y;      // 0..3  H chunk
    const int b   = blockIdx.z;      // 0..31 batch
    const int c   = cb * 32 + tx * 4;

    // 3x3 per-channel weights; center tap := 1.0 (residual fold)
    float4 Wt[3][3];
#pragma unroll
    for (int ky = 0; ky < 3; ky++)
#pragma unroll
        for (int kx = 0; kx < 3; kx++)
            Wt[ky][kx] = *reinterpret_cast<const float4*>(krn + (ky * 3 + kx) * C_ + c);
    Wt[1][1] = make_float4(1.f, 1.f, 1.f, 1.f);

    const int  w0  = ty * 2;
    const bool wlo = (w0 > 0);           // col w0-1 exists
    const bool whi = (w0 + 2 < W_);      // col w1+1 exists
    const float4 z = make_float4(0.f, 0.f, 0.f, 0.f);

    const size_t base = (size_t)b * H_ * ROWF4 + (size_t)w0 * CQ + cb * CG + tx;
    const float4* xb = x   + base;
    float4*       ob = out + base;

    const int hs = hch * HC;

    // row loader: cols w0-1, w0, w0+1, w0+2 of input row r (zeros OOB)
    auto load = [&](int r, float4* v) {
        if ((unsigned)r < (unsigned)H_) {
            const float4* p = xb + (size_t)r * ROWF4;
            v[0] = wlo ? p[-CQ]    : z;
            v[1] = p[0];
            v[2] = p[CQ];
            v[3] = whi ? p[2 * CQ] : z;
        } else {
            v[0] = z; v[1] = z; v[2] = z; v[3] = z;
        }
    };

    // horizontal conv of v[0..3] with weight row k, accumulated into (o0,o1)
    auto hconv = [&](float4& o0, float4& o1, const float4 k0, const float4 k1,
                     const float4 k2, const float4* v) {
        o0.x = fmaf(k0.x, v[0].x, fmaf(k1.x, v[1].x, fmaf(k2.x, v[2].x, o0.x)));
        o0.y = fmaf(k0.y, v[0].y, fmaf(k1.y, v[1].y, fmaf(k2.y, v[2].y, o0.y)));
        o0.z = fmaf(k0.z, v[0].z, fmaf(k1.z, v[1].z, fmaf(k2.z, v[2].z, o0.z)));
        o0.w = fmaf(k0.w, v[0].w, fmaf(k1.w, v[1].w, fmaf(k2.w, v[2].w, o0.w)));
        o1.x = fmaf(k0.x, v[1].x, fmaf(k1.x, v[2].x, fmaf(k2.x, v[3].x, o1.x)));
        o1.y = fmaf(k0.y, v[1].y, fmaf(k1.y, v[2].y, fmaf(k2.y, v[3].y, o1.y)));
        o1.z = fmaf(k0.z, v[1].z, fmaf(k1.z, v[2].z, fmaf(k2.z, v[3].z, o1.z)));
        o1.w = fmaf(k0.w, v[1].w, fmaf(k1.w, v[2].w, fmaf(k2.w, v[3].w, o1.w)));
    };

    float4 buf[4][4];               // 4-slot register row ring
    float4 am0 = z, am1 = z;        // partial accum for output row r-1
    float4 ac0 = z, ac1 = z;        // partial accum for output row r

    // prolog: rows hs-1 .. hs+2 into slots 0..3 (16 LDG issued back-to-back)
    load(hs - 1, buf[0]);
    load(hs,     buf[1]);
    load(hs + 1, buf[2]);
    load(hs + 2, buf[3]);

    // iterations i = 0..HC+1 consume input rows hs-1 .. hs+HC
#pragma unroll
    for (int i = 0; i < HC + 2; i++) {
        const int r = hs - 1 + i;
        const float4* cur = buf[i % 4];

        // complete output row r-1 with this row's bottom-tap contribution
        float4 d0 = am0, d1 = am1;
        hconv(d0, d1, Wt[2][0], Wt[2][1], Wt[2][2], cur);
        if (i >= 2) {               // output rows hs .. hs+HC-1
            float4* po = ob + (size_t)(r - 1) * ROWF4;
            po[0]  = d0;
            po[CQ] = d1;
        }

        // roll accumulators: am <- ac + middle-tap, ac <- top-tap (fresh)
        am0 = ac0; am1 = ac1;
        hconv(am0, am1, Wt[1][0], Wt[1][1], Wt[1][2], cur);
        ac0 = z; ac1 = z;
        hconv(ac0, ac1, Wt[0][0], Wt[0][1], Wt[0][2], cur);

        // refill the slot just consumed with row r+4 (consumed at i+4)
        if (i <= HC - 3)
            load(r + 4, buf[i % 4]);
    }
}

extern "C" void kernel_launch(void* const* d_in, const int* in_sizes, int n_in,
                              void* d_out, int out_size)
{
    const float4* x   = (const float4*)d_in[0];
    const float*  krn = (const float*)d_in[1];
    float4*       out = (float4*)d_out;

    dim3 block(CG, W_ / 2, 1);               // 224 threads
    dim3 grid(C_ / (CG * 4), H_ / HC, B_);   // 8 x 4 x 32 = 1024 blocks
    contour_kernel<<<grid, block>>>(x, krn, out);
}